// round 9
// baseline (speedup 1.0000x reference)
#include <cuda_runtime.h>

#define DIM      4096
#define B        8
#define KV_DIM   1024   // N_KV_HEADS * HEAD_DIM
#define TOTAL    16384
#define O_TILE   8      // output columns per fused block

// Scratch (allocation-free rule: __device__ globals)
__device__ __align__(16) float g_x[B * KV_DIM];  // up-proj result [b][r]

__device__ __forceinline__ float dot4(float4 a, float4 b) {
    return a.x * b.x + a.y * b.y + a.z * b.z + a.w * b.w;
}

// ---------------------------------------------------------------------------
// Kernel 1: x[b][r] = sum_k emb[b][k] * Wup[r][k]
// ONE row per block, grid = 1024, 256 threads (8 warps split the reduction).
// Each thread: 4 independent DRAM W loads (single latency round), then
// 32 L1-hit emb loads. emb is read exactly once per block (no redundancy)
// and stays L1-resident across the ~7 blocks that share each SM.
// ---------------------------------------------------------------------------
__global__ void __launch_bounds__(256) up_proj_kernel(
    const float* __restrict__ emb, const float* __restrict__ Wup)
{
    const int r    = blockIdx.x;        // 0..1023
    const int tid  = threadIdx.x;
    const int lane = tid & 31;
    const int wid  = tid >> 5;          // 0..7 : k-slice of 128 float4
    const float4* w4 = reinterpret_cast<const float4*>(Wup + (size_t)r * DIM);
    const float4* e4 = reinterpret_cast<const float4*>(emb);

    // 4 independent DRAM loads, front-batched.
    float4 w[4];
#pragma unroll
    for (int s = 0; s < 4; s++) w[s] = __ldg(&w4[wid * 128 + s * 32 + lane]);

    float acc[B];
#pragma unroll
    for (int b = 0; b < B; b++) acc[b] = 0.f;

#pragma unroll
    for (int s = 0; s < 4; s++) {
        const int q = wid * 128 + s * 32 + lane;
#pragma unroll
        for (int b = 0; b < B; b++) {
            const float4 e = __ldg(&e4[(size_t)b * 1024 + q]);
            acc[b] += dot4(w[s], e);
        }
    }

    __shared__ float s_part[8][B];      // [warp][b]
#pragma unroll
    for (int b = 0; b < B; b++) {
        float v = acc[b];
#pragma unroll
        for (int off = 16; off; off >>= 1) v += __shfl_down_sync(0xffffffffu, v, off);
        if (lane == 0) s_part[wid][b] = v;
    }
    __syncthreads();
    if (tid < B) {                      // tid = b
        float v = 0.f;
#pragma unroll
        for (int w8 = 0; w8 < 8; w8++) v += s_part[w8][tid];
        g_x[tid * KV_DIM + r] = v;
    }
}

// ---------------------------------------------------------------------------
// Kernel 2 (FUSED down_proj + broadcast), O_TILE=8 cols, 512 threads, grid=512.
//
// Phase A: y[b][o] = sum_j val[b][j] * Wdown[o][j] for the 8 columns.
//   val[b][j] = x[b][((j>>9)<<7)|(j&127)]  (repeat-interleave remap).
//   16 warps = 4 k-slices x 4 row-pairs; per-thread acc[2][B] keeps registers
//   <=62 so 2 CTAs co-reside per SM (~32 warps/SM).
//   Wdown (64 MB chip-wide) is read exactly once from DRAM.
//
// Phase B: the 8x8 y-tile is broadcast from smem-backed registers to all
//   16384 token rows with streaming STG.128 (64 stores/thread).
// ---------------------------------------------------------------------------
__global__ void __launch_bounds__(512, 2) fused_down_bcast_kernel(
    const float* __restrict__ Wdown, const int* __restrict__ seqlen_raw,
    float* __restrict__ out)
{
    const int tid  = threadIdx.x;
    const int lane = tid & 31;
    const int wid  = tid >> 5;           // 0..15
    const int o0   = blockIdx.x * O_TILE;

    // --- seqlen prefix (int32/int64 auto-detect) ---
    __shared__ int s_off[B + 1];
    if (tid == 0) {
        int sum32 = 0;
#pragma unroll
        for (int i = 0; i < B; i++) sum32 += seqlen_raw[i];
        const bool is64 = (sum32 != TOTAL);
        int acc = 0;
#pragma unroll
        for (int i = 0; i < B; i++) {
            s_off[i] = acc;
            acc += is64 ? seqlen_raw[2 * i] : seqlen_raw[i];
        }
        s_off[B] = acc;
    }

    // ---------------- Phase A: compute the 8 x 8 y-tile ----------------
    const int ks = wid >> 2;             // 0..3 : k-slice (256 float4 each)
    const int rg = wid & 3;              // 0..3 : row pair
    const int ra = o0 + rg * 2;          // rows ra, ra+1
    const float4* Wd4 = reinterpret_cast<const float4*>(Wdown);

    float acc[2][B];
#pragma unroll
    for (int i = 0; i < 2; i++)
#pragma unroll
        for (int b = 0; b < B; b++) acc[i][b] = 0.f;

#pragma unroll
    for (int s = 0; s < 8; s++) {
        const int q = ks * 256 + s * 32 + lane;          // float4 idx in [0,1024)
        const float4 w0 = __ldg(&Wd4[(size_t)ra * 1024 + q]);
        const float4 w1 = __ldg(&Wd4[(size_t)(ra + 1) * 1024 + q]);
        const int j0 = 4 * q;
        const int m0 = ((j0 >> 9) << 7) | (j0 & 127);    // remap, float4-aligned
#pragma unroll
        for (int b = 0; b < B; b++) {
            const float4 xv = *reinterpret_cast<const float4*>(&g_x[b * KV_DIM + m0]);
            acc[0][b] += dot4(w0, xv);
            acc[1][b] += dot4(w1, xv);
        }
    }

    __shared__ float s_part[4][O_TILE][B];   // [ks][row][b]
#pragma unroll
    for (int i = 0; i < 2; i++)
#pragma unroll
        for (int b = 0; b < B; b++) {
            float v = acc[i][b];
#pragma unroll
            for (int off = 16; off; off >>= 1) v += __shfl_down_sync(0xffffffffu, v, off);
            if (lane == 0) s_part[ks][rg * 2 + i][b] = v;
        }
    __syncthreads();

    __shared__ __align__(16) float y_s[B][O_TILE];
    if (tid < 64) {
        const int row = tid >> 3, b = tid & 7;
        y_s[b][row] = s_part[0][row][b] + s_part[1][row][b]
                    + s_part[2][row][b] + s_part[3][row][b];
    }
    __syncthreads();

    // ---------------- Phase B: broadcast tile to all tokens ----------------
    // thread -> (col4, slot): col4 picks one of 2 float4 columns of the tile,
    // slot picks the token residue mod 256.
    const int col4 = tid & 1;
    const int slot = tid >> 1;           // 0..255

    float4 yv[B];
#pragma unroll
    for (int b = 0; b < B; b++)
        yv[b] = *reinterpret_cast<const float4*>(&y_s[b][col4 * 4]);

    float4* out4 = reinterpret_cast<float4*>(out) + (o0 >> 2) + col4;

#pragma unroll
    for (int b = 0; b < B; b++) {
        const float4 v = yv[b];                          // compile-time index
        const int lo = s_off[b], hi = s_off[b + 1];
        int t = lo + ((slot - lo) & 255);                // first token >= lo, t%256==slot
        for (; t < hi; t += 256)
            __stcs(out4 + (size_t)t * 1024, v);
    }
}

// ---------------------------------------------------------------------------
// Inputs (metadata order): embedding [8,4096] f32, W_up [1024,4096] f32,
// W_down [4096,4096] f32, seqlen [8] int. Output: [16384,4096] f32.
// ---------------------------------------------------------------------------
extern "C" void kernel_launch(void* const* d_in, const int* in_sizes, int n_in,
                              void* d_out, int out_size)
{
    const float* emb    = (const float*)d_in[0];
    const float* Wup    = (const float*)d_in[1];
    const float* Wdown  = (const float*)d_in[2];
    const int*   seqlen = (const int*)d_in[3];
    float* out = (float*)d_out;

    up_proj_kernel<<<KV_DIM, 256>>>(emb, Wup);
    fused_down_bcast_kernel<<<DIM / O_TILE, 512>>>(Wdown, seqlen, out);
}

// round 11
// speedup vs baseline: 1.1486x; 1.1486x over previous
#include <cuda_runtime.h>

#define DIM      4096
#define B        8
#define KV_DIM   1024   // N_KV_HEADS * HEAD_DIM
#define TOTAL    16384

// Scratch (allocation-free rule: __device__ globals)
__device__ __align__(16) float g_x[B * KV_DIM];  // up-proj result  [b][r]
__device__ __align__(16) float g_y[B * DIM];     // down-proj result [b][o]

__device__ __forceinline__ float dot4(float4 a, float4 b) {
    return a.x * b.x + a.y * b.y + a.z * b.z + a.w * b.w;
}

// ---------------------------------------------------------------------------
// Kernel 1: x[b][r] = sum_k emb[b][k] * Wup[r][k]
// 4 rows per block (register blocking), grid=256, 256 threads (8 warps, each
// owning a 128-float4 k-slice). Each emb load feeds 4 rows; each W load feeds
// 8 batches. Per thread: 16 independent DRAM W loads + 32 L1-hot emb loads.
// ---------------------------------------------------------------------------
__global__ void __launch_bounds__(256) up_proj_kernel(
    const float* __restrict__ emb, const float* __restrict__ Wup)
{
    const int tid  = threadIdx.x;
    const int lane = tid & 31;
    const int wid  = tid >> 5;          // 0..7 : k-slice
    const int r0   = blockIdx.x * 4;    // rows r0..r0+3
    const float4* w4 = reinterpret_cast<const float4*>(Wup);
    const float4* e4 = reinterpret_cast<const float4*>(emb);

    float acc[4][B];
#pragma unroll
    for (int i = 0; i < 4; i++)
#pragma unroll
        for (int b = 0; b < B; b++) acc[i][b] = 0.f;

#pragma unroll
    for (int s = 0; s < 4; s++) {
        const int q = wid * 128 + s * 32 + lane;   // float4 idx in [0,1024)
        float4 w[4];
#pragma unroll
        for (int i = 0; i < 4; i++)
            w[i] = __ldg(&w4[(size_t)(r0 + i) * 1024 + q]);
#pragma unroll
        for (int b = 0; b < B; b++) {
            const float4 e = __ldg(&e4[(size_t)b * 1024 + q]);
#pragma unroll
            for (int i = 0; i < 4; i++) acc[i][b] += dot4(w[i], e);
        }
    }

    __shared__ float s_part[8][4][B];   // [warp][row][b]
#pragma unroll
    for (int i = 0; i < 4; i++)
#pragma unroll
        for (int b = 0; b < B; b++) {
            float v = acc[i][b];
#pragma unroll
            for (int off = 16; off; off >>= 1) v += __shfl_down_sync(0xffffffffu, v, off);
            if (lane == 0) s_part[wid][i][b] = v;
        }
    __syncthreads();
    if (tid < 32) {
        const int row = tid >> 3, b = tid & 7;
        float v = 0.f;
#pragma unroll
        for (int w8 = 0; w8 < 8; w8++) v += s_part[w8][row][b];
        g_x[b * KV_DIM + r0 + row] = v;
    }
}

// ---------------------------------------------------------------------------
// Kernel 2: y[b][o] = sum_j val[b][j] * Wdown[o][j]
//   val[b][j] = x[b][((j>>9)<<7)|(j&127)]  (repeat-interleave remap).
// Same 4-row register-blocked structure: grid=1024, 256 threads.
// Wdown (64 MB) read exactly once; g_x (32 KB) L1-resident.
// ---------------------------------------------------------------------------
__global__ void __launch_bounds__(256) down_proj_kernel(
    const float* __restrict__ Wdown)
{
    const int tid  = threadIdx.x;
    const int lane = tid & 31;
    const int wid  = tid >> 5;          // 0..7 : k-slice
    const int r0   = blockIdx.x * 4;    // rows r0..r0+3 of 4096
    const float4* w4 = reinterpret_cast<const float4*>(Wdown);

    float acc[4][B];
#pragma unroll
    for (int i = 0; i < 4; i++)
#pragma unroll
        for (int b = 0; b < B; b++) acc[i][b] = 0.f;

#pragma unroll
    for (int s = 0; s < 4; s++) {
        const int q = wid * 128 + s * 32 + lane;         // float4 idx in [0,1024)
        float4 w[4];
#pragma unroll
        for (int i = 0; i < 4; i++)
            w[i] = __ldg(&w4[(size_t)(r0 + i) * 1024 + q]);
        const int j0 = 4 * q;
        const int m0 = ((j0 >> 9) << 7) | (j0 & 127);    // remap, float4-aligned
#pragma unroll
        for (int b = 0; b < B; b++) {
            const float4 xv = *reinterpret_cast<const float4*>(&g_x[b * KV_DIM + m0]);
#pragma unroll
            for (int i = 0; i < 4; i++) acc[i][b] += dot4(w[i], xv);
        }
    }

    __shared__ float s_part[8][4][B];
#pragma unroll
    for (int i = 0; i < 4; i++)
#pragma unroll
        for (int b = 0; b < B; b++) {
            float v = acc[i][b];
#pragma unroll
            for (int off = 16; off; off >>= 1) v += __shfl_down_sync(0xffffffffu, v, off);
            if (lane == 0) s_part[wid][i][b] = v;
        }
    __syncthreads();
    if (tid < 32) {
        const int row = tid >> 3, b = tid & 7;
        float v = 0.f;
#pragma unroll
        for (int w8 = 0; w8 < 8; w8++) v += s_part[w8][row][b];
        g_y[b * DIM + r0 + row] = v;
    }
}

// ---------------------------------------------------------------------------
// Kernel 3: out[t][:] = y[batch(t)][:]  — 256 MB, HBM-write-bound.
// ONE TOKEN PER 128-THREAD HALF-BLOCK: 128 threads x 8 float4 = 1024 float4
// = exactly one full 16 KB row, contiguous streaming stores. Adjacent
// half-blocks/blocks write adjacent rows -> maximal DRAM locality.
// y (128 KB) is L1-resident per SM, so reads are free under the write stream.
// grid = 8192 blocks x 256 threads (2 tokens per block).
// ---------------------------------------------------------------------------
__global__ void __launch_bounds__(256) broadcast_kernel(
    const int* __restrict__ seqlen_raw, float* __restrict__ out)
{
    __shared__ int s_off[B + 1];
    if (threadIdx.x == 0) {
        int sum32 = 0;
#pragma unroll
        for (int i = 0; i < B; i++) sum32 += seqlen_raw[i];
        const bool is64 = (sum32 != TOTAL);   // int64: low word at 2*i (LE)
        int acc = 0;
#pragma unroll
        for (int i = 0; i < B; i++) {
            s_off[i] = acc;
            acc += is64 ? seqlen_raw[2 * i] : seqlen_raw[i];
        }
        s_off[B] = acc;
    }
    __syncthreads();

    const int sub   = threadIdx.x & 127;                      // 0..127
    const int token = blockIdx.x * 2 + (threadIdx.x >> 7);    // one token per half-block

    int b = 0;
#pragma unroll
    for (int i = 1; i < B; i++) b += (token >= s_off[i]);

    const float4* y4 = reinterpret_cast<const float4*>(&g_y[b * DIM]);
    float4* o4 = reinterpret_cast<float4*>(out) + (size_t)token * 1024;

    // batch the 8 L1-hit loads, then 8 contiguous streaming stores
    // covers sub + k*128 for k=0..7  ->  all 1024 float4 of the row
    float4 v[8];
#pragma unroll
    for (int k = 0; k < 8; k++) v[k] = __ldg(&y4[sub + k * 128]);
#pragma unroll
    for (int k = 0; k < 8; k++) __stcs(&o4[sub + k * 128], v[k]);
}

// ---------------------------------------------------------------------------
// Inputs (metadata order): embedding [8,4096] f32, W_up [1024,4096] f32,
// W_down [4096,4096] f32, seqlen [8] int. Output: [16384,4096] f32.
// ---------------------------------------------------------------------------
extern "C" void kernel_launch(void* const* d_in, const int* in_sizes, int n_in,
                              void* d_out, int out_size)
{
    const float* emb    = (const float*)d_in[0];
    const float* Wup    = (const float*)d_in[1];
    const float* Wdown  = (const float*)d_in[2];
    const int*   seqlen = (const int*)d_in[3];
    float* out = (float*)d_out;

    up_proj_kernel<<<KV_DIM / 4, 256>>>(emb, Wup);
    down_proj_kernel<<<DIM / 4, 256>>>(Wdown);
    broadcast_kernel<<<TOTAL / 2, 256>>>(seqlen, out);
}

// round 12
// speedup vs baseline: 1.1610x; 1.0108x over previous
#include <cuda_runtime.h>

#define DIM      4096
#define B        8
#define KV_DIM   1024   // N_KV_HEADS * HEAD_DIM
#define TOTAL    16384

// Scratch (allocation-free rule: __device__ globals)
__device__ __align__(16) float g_x[B * KV_DIM];  // up-proj result  [b][r]
__device__ __align__(16) float g_y[B * DIM];     // down-proj result [b][o]

__device__ __forceinline__ float dot4(float4 a, float4 b) {
    return a.x * b.x + a.y * b.y + a.z * b.z + a.w * b.w;
}

// ---------------------------------------------------------------------------
// Kernel 1: x[b][r] = sum_k emb[b][k] * Wup[r][k]
// 2 rows per block, grid=512, 256 threads (8 warps, each owning a 128-float4
// k-slice). ~48 regs -> 4-5 CTAs/SM resident (vs 1.7 at R11's 4-row/256-grid).
// emb (128 KB) is L1-resident per SM; W rows are the only DRAM traffic.
// ---------------------------------------------------------------------------
__global__ void __launch_bounds__(256) up_proj_kernel(
    const float* __restrict__ emb, const float* __restrict__ Wup)
{
    const int tid  = threadIdx.x;
    const int lane = tid & 31;
    const int wid  = tid >> 5;          // 0..7 : k-slice
    const int r0   = blockIdx.x * 2;    // rows r0, r0+1
    const float4* w4 = reinterpret_cast<const float4*>(Wup);
    const float4* e4 = reinterpret_cast<const float4*>(emb);

    float acc[2][B];
#pragma unroll
    for (int i = 0; i < 2; i++)
#pragma unroll
        for (int b = 0; b < B; b++) acc[i][b] = 0.f;

#pragma unroll
    for (int s = 0; s < 4; s++) {
        const int q = wid * 128 + s * 32 + lane;   // float4 idx in [0,1024)
        const float4 w0 = __ldg(&w4[(size_t)r0 * 1024 + q]);
        const float4 w1 = __ldg(&w4[(size_t)(r0 + 1) * 1024 + q]);
#pragma unroll
        for (int b = 0; b < B; b++) {
            const float4 e = __ldg(&e4[(size_t)b * 1024 + q]);
            acc[0][b] += dot4(w0, e);
            acc[1][b] += dot4(w1, e);
        }
    }

    __shared__ float s_part[8][2][B];   // [warp][row][b]
#pragma unroll
    for (int i = 0; i < 2; i++)
#pragma unroll
        for (int b = 0; b < B; b++) {
            float v = acc[i][b];
#pragma unroll
            for (int off = 16; off; off >>= 1) v += __shfl_down_sync(0xffffffffu, v, off);
            if (lane == 0) s_part[wid][i][b] = v;
        }
    __syncthreads();
    if (tid < 16) {
        const int row = tid >> 3, b = tid & 7;
        float v = 0.f;
#pragma unroll
        for (int w8 = 0; w8 < 8; w8++) v += s_part[w8][row][b];
        g_x[b * KV_DIM + r0 + row] = v;
    }
}

// ---------------------------------------------------------------------------
// Kernel 2: y[b][o] = sum_j val[b][j] * Wdown[o][j]
//   val[b][j] = x[b][((j>>9)<<7)|(j&127)]  (repeat-interleave remap).
// 2 rows per block, grid=2048, 256 threads. Wdown (64 MB) read exactly once;
// g_x (32 KB) L1-resident. High CTA count -> latency fully hidden.
// ---------------------------------------------------------------------------
__global__ void __launch_bounds__(256) down_proj_kernel(
    const float* __restrict__ Wdown)
{
    const int tid  = threadIdx.x;
    const int lane = tid & 31;
    const int wid  = tid >> 5;          // 0..7 : k-slice
    const int r0   = blockIdx.x * 2;    // rows r0, r0+1 of 4096
    const float4* w4 = reinterpret_cast<const float4*>(Wdown);

    float acc[2][B];
#pragma unroll
    for (int i = 0; i < 2; i++)
#pragma unroll
        for (int b = 0; b < B; b++) acc[i][b] = 0.f;

#pragma unroll
    for (int s = 0; s < 4; s++) {
        const int q = wid * 128 + s * 32 + lane;         // float4 idx in [0,1024)
        const float4 w0 = __ldg(&w4[(size_t)r0 * 1024 + q]);
        const float4 w1 = __ldg(&w4[(size_t)(r0 + 1) * 1024 + q]);
        const int j0 = 4 * q;
        const int m0 = ((j0 >> 9) << 7) | (j0 & 127);    // remap, float4-aligned
#pragma unroll
        for (int b = 0; b < B; b++) {
            const float4 xv = *reinterpret_cast<const float4*>(&g_x[b * KV_DIM + m0]);
            acc[0][b] += dot4(w0, xv);
            acc[1][b] += dot4(w1, xv);
        }
    }

    __shared__ float s_part[8][2][B];
#pragma unroll
    for (int i = 0; i < 2; i++)
#pragma unroll
        for (int b = 0; b < B; b++) {
            float v = acc[i][b];
#pragma unroll
            for (int off = 16; off; off >>= 1) v += __shfl_down_sync(0xffffffffu, v, off);
            if (lane == 0) s_part[wid][i][b] = v;
        }
    __syncthreads();
    if (tid < 16) {
        const int row = tid >> 3, b = tid & 7;
        float v = 0.f;
#pragma unroll
        for (int w8 = 0; w8 < 8; w8++) v += s_part[w8][row][b];
        g_y[b * DIM + r0 + row] = v;
    }
}

// ---------------------------------------------------------------------------
// Kernel 3: out[t][:] = y[batch(t)][:]  — 256 MB, HBM-write-bound.
// One token per 128-thread half-block: 128 threads x 8 float4 = exactly one
// full 16 KB row, contiguous streaming stores. Adjacent half-blocks write
// adjacent rows. y (128 KB) is L1-resident so reads ride under the writes.
// grid = 8192 blocks x 256 threads (2 tokens per block).
// ---------------------------------------------------------------------------
__global__ void __launch_bounds__(256) broadcast_kernel(
    const int* __restrict__ seqlen_raw, float* __restrict__ out)
{
    __shared__ int s_off[B + 1];
    if (threadIdx.x == 0) {
        int sum32 = 0;
#pragma unroll
        for (int i = 0; i < B; i++) sum32 += seqlen_raw[i];
        const bool is64 = (sum32 != TOTAL);   // int64: low word at 2*i (LE)
        int acc = 0;
#pragma unroll
        for (int i = 0; i < B; i++) {
            s_off[i] = acc;
            acc += is64 ? seqlen_raw[2 * i] : seqlen_raw[i];
        }
        s_off[B] = acc;
    }
    __syncthreads();

    const int sub   = threadIdx.x & 127;                      // 0..127
    const int token = blockIdx.x * 2 + (threadIdx.x >> 7);    // one token per half-block

    int b = 0;
#pragma unroll
    for (int i = 1; i < B; i++) b += (token >= s_off[i]);

    const float4* y4 = reinterpret_cast<const float4*>(&g_y[b * DIM]);
    float4* o4 = reinterpret_cast<float4*>(out) + (size_t)token * 1024;

    float4 v[8];
#pragma unroll
    for (int k = 0; k < 8; k++) v[k] = __ldg(&y4[sub + k * 128]);
#pragma unroll
    for (int k = 0; k < 8; k++) __stcs(&o4[sub + k * 128], v[k]);
}

// ---------------------------------------------------------------------------
// Inputs (metadata order): embedding [8,4096] f32, W_up [1024,4096] f32,
// W_down [4096,4096] f32, seqlen [8] int. Output: [16384,4096] f32.
// ---------------------------------------------------------------------------
extern "C" void kernel_launch(void* const* d_in, const int* in_sizes, int n_in,
                              void* d_out, int out_size)
{
    const float* emb    = (const float*)d_in[0];
    const float* Wup    = (const float*)d_in[1];
    const float* Wdown  = (const float*)d_in[2];
    const int*   seqlen = (const int*)d_in[3];
    float* out = (float*)d_out;

    up_proj_kernel<<<KV_DIM / 2, 256>>>(emb, Wup);
    down_proj_kernel<<<DIM / 2, 256>>>(Wdown);
    broadcast_kernel<<<TOTAL / 2, 256>>>(seqlen, out);
}